// round 12
// baseline (speedup 1.0000x reference)
#include <cuda_runtime.h>
#include <cuda_bf16.h>
#include <cstddef>
#include <cstdint>

#define B_ 8
#define N_ 4096
#define S_ 4096
#define D_ 1024
#define H_ 16
#define A_ 8
#define DH 64
#define NA 512
#define KKEEP 2048
#define SCALE_ 0.125f

// bf16 mma tiling: BM=128, BN=128, BK=32 (2 x k16 steps), pitch 80B rows
#define BM 128
#define BN 128
#define ARRB 10240              // bytes per array: 128 rows * 80
#define STAGE_B 40960           // Ah+Al+Bh+Bl
#define SMEM_MMA 81920          // 2 stages

__device__ float g_kc[(size_t)B_ * S_ * D_];
__device__ float g_vc[(size_t)B_ * S_ * D_];
__device__ float g_qo[(size_t)B_ * N_ * D_];
__device__ float g_attn_agent[(size_t)B_ * H_ * A_ * S_];
__device__ float g_agent_raw[B_ * A_ * D_];
__device__ float g_agent_tok[B_ * A_ * D_];
__device__ float g_qa[B_ * A_ * D_];
__device__ float g_ka[B_ * A_ * D_];
__device__ float g_va[B_ * A_ * D_];
__device__ float g_agent_out[B_ * A_ * D_];
// bf16 split operands
__device__ __nv_bfloat16 g_ah[(size_t)B_ * N_ * D_];
__device__ __nv_bfloat16 g_al[(size_t)B_ * N_ * D_];
__device__ __nv_bfloat16 g_ah2[(size_t)B_ * N_ * D_];
__device__ __nv_bfloat16 g_al2[(size_t)B_ * N_ * D_];
__device__ __nv_bfloat16 g_bh1[(size_t)D_ * D_], g_bl1[(size_t)D_ * D_];
__device__ __nv_bfloat16 g_bh2[(size_t)D_ * D_], g_bl2[(size_t)D_ * D_];
__device__ __nv_bfloat16 g_bh3[(size_t)D_ * D_], g_bl3[(size_t)D_ * D_];

__device__ __forceinline__ uint32_t smem_u32(const void* p) {
    uint32_t a;
    asm("{ .reg .u64 t; cvta.to.shared.u64 t, %1; cvt.u32.u64 %0, t; }" : "=r"(a) : "l"(p));
    return a;
}
#define CP_ASYNC16(dst, src) \
    asm volatile("cp.async.cg.shared.global [%0], [%1], 16;" :: "r"(dst), "l"(src) : "memory")
#define CP_COMMIT() asm volatile("cp.async.commit_group;" ::: "memory")
#define CP_WAITN(n) asm volatile("cp.async.wait_group %0;" :: "n"(n) : "memory")

__device__ __forceinline__ void mma16(float* d, const uint32_t* a, uint32_t b0, uint32_t b1) {
    asm volatile(
        "mma.sync.aligned.m16n8k16.row.col.f32.bf16.bf16.f32 "
        "{%0,%1,%2,%3}, {%4,%5,%6,%7}, {%8,%9}, {%0,%1,%2,%3};"
        : "+f"(d[0]), "+f"(d[1]), "+f"(d[2]), "+f"(d[3])
        : "r"(a[0]), "r"(a[1]), "r"(a[2]), "r"(a[3]), "r"(b0), "r"(b1));
}

__device__ __forceinline__ void bf16_split(float v, __nv_bfloat16& h, __nv_bfloat16& l) {
    h = __float2bfloat16_rn(v);
    l = __float2bfloat16_rn(v - __bfloat162float(h));
}
__device__ __forceinline__ uint32_t pk2(__nv_bfloat16 a, __nv_bfloat16 b) {
    return (uint32_t)__bfloat16_as_ushort(a) | ((uint32_t)__bfloat16_as_ushort(b) << 16);
}

// A[M,1024] fp32 -> bf16 hi/lo (row-major). 8 floats/thread.
__global__ __launch_bounds__(256) void split_a_bf16(const float* __restrict__ a,
                                                    __nv_bfloat16* __restrict__ hi,
                                                    __nv_bfloat16* __restrict__ lo) {
    size_t i = (size_t)blockIdx.x * 256 + threadIdx.x;
    const float4* s4 = (const float4*)a + i * 2;
    float4 x = s4[0], y = s4[1];
    float v[8] = {x.x, x.y, x.z, x.w, y.x, y.y, y.z, y.w};
    uint32_t hp[4], lp[4];
#pragma unroll
    for (int j = 0; j < 4; j++) {
        __nv_bfloat16 h0, l0, h1, l1;
        bf16_split(v[2 * j], h0, l0);
        bf16_split(v[2 * j + 1], h1, l1);
        hp[j] = pk2(h0, h1);
        lp[j] = pk2(l0, l1);
    }
    *(uint4*)(hi + i * 8) = make_uint4(hp[0], hp[1], hp[2], hp[3]);
    *(uint4*)(lo + i * 8) = make_uint4(lp[0], lp[1], lp[2], lp[3]);
}

// W[k][n] fp32 -> bf16 hi/lo transposed [n][k]
__global__ __launch_bounds__(256) void split_w_bf16(const float* __restrict__ w,
                                                    __nv_bfloat16* __restrict__ hi,
                                                    __nv_bfloat16* __restrict__ lo) {
    __shared__ float t[32][33];
    int k0 = blockIdx.y * 32, n0 = blockIdx.x * 32;
    int tx = threadIdx.x, ty = threadIdx.y;
    for (int i = ty; i < 32; i += 8)
        t[i][tx] = w[(size_t)(k0 + i) * 1024 + n0 + tx];
    __syncthreads();
    for (int i = ty; i < 32; i += 8) {
        __nv_bfloat16 h, l;
        bf16_split(t[tx][i], h, l);
        hi[(size_t)(n0 + i) * 1024 + k0 + tx] = h;
        lo[(size_t)(n0 + i) * 1024 + k0 + tx] = l;
    }
}

// C[M,1024] = (Ah+Al)@(Bh+Bl)^T + bias, 3xBF16 m16n8k16. grid=(8, M/128), 2 CTA/SM
__global__ __launch_bounds__(256, 2) void mma_gemm_kernel(
    const __nv_bfloat16* __restrict__ gAh, const __nv_bfloat16* __restrict__ gAl,
    const __nv_bfloat16* __restrict__ gBh, const __nv_bfloat16* __restrict__ gBl,
    const float* __restrict__ bias, float* __restrict__ C) {
    extern __shared__ __align__(16) char smem[];
    const int tid = threadIdx.x;
    const int row0 = blockIdx.y * BM;
    const int col0 = blockIdx.x * BN;
    const int w = tid >> 5;
    const int lane = tid & 31;
    const int wm = w >> 2;
    const int wn = w & 3;
    const int g = lane >> 2;
    const int ctg = lane & 3;

    float acc[4][4][4];
#pragma unroll
    for (int mt = 0; mt < 4; mt++)
#pragma unroll
        for (int nt = 0; nt < 4; nt++)
#pragma unroll
            for (int r = 0; r < 4; r++) acc[mt][nt][r] = 0.f;

    auto load_stage = [&](int s, int kt) {
        char* st = smem + s * STAGE_B;
        const int k0 = kt * 32;
#pragma unroll
        for (int j = 0; j < 2; j++) {
            int cid = j * 256 + tid;
            int r = cid >> 2, c = cid & 3;
            uint32_t da = smem_u32(st + r * 80 + c * 16);
            size_t ga = (size_t)(row0 + r) * 1024 + k0 + c * 8;
            CP_ASYNC16(da, gAh + ga);
            CP_ASYNC16(da + ARRB, gAl + ga);
            uint32_t db = smem_u32(st + 2 * ARRB + r * 80 + c * 16);
            size_t gb = (size_t)(col0 + r) * 1024 + k0 + c * 8;
            CP_ASYNC16(db, gBh + gb);
            CP_ASYNC16(db + ARRB, gBl + gb);
        }
        CP_COMMIT();
    };

    load_stage(0, 0);

    for (int kt = 0; kt < 32; kt++) {
        if (kt + 1 < 32) {
            load_stage((kt + 1) & 1, kt + 1);
            CP_WAITN(1);
        } else {
            CP_WAITN(0);
        }
        __syncthreads();
        const char* st = smem + (kt & 1) * STAGE_B;
#pragma unroll
        for (int ks = 0; ks < 2; ks++) {
            const int ko = ks * 32;
            uint32_t ah[4][4], al[4][4];
#pragma unroll
            for (int mt = 0; mt < 4; mt++) {
                int r = wm * 64 + mt * 16 + g;
                const char* pa = st + r * 80 + ko + ctg * 4;
                ah[mt][0] = *(const uint32_t*)(pa);
                ah[mt][1] = *(const uint32_t*)(pa + 8 * 80);
                ah[mt][2] = *(const uint32_t*)(pa + 16);
                ah[mt][3] = *(const uint32_t*)(pa + 8 * 80 + 16);
                const char* pl = pa + ARRB;
                al[mt][0] = *(const uint32_t*)(pl);
                al[mt][1] = *(const uint32_t*)(pl + 8 * 80);
                al[mt][2] = *(const uint32_t*)(pl + 16);
                al[mt][3] = *(const uint32_t*)(pl + 8 * 80 + 16);
            }
#pragma unroll
            for (int nt = 0; nt < 4; nt++) {
                int n = wn * 32 + nt * 8 + g;
                const char* pb = st + 2 * ARRB + n * 80 + ko + ctg * 4;
                uint32_t bh0 = *(const uint32_t*)(pb);
                uint32_t bh1 = *(const uint32_t*)(pb + 16);
                uint32_t bl0 = *(const uint32_t*)(pb + ARRB);
                uint32_t bl1 = *(const uint32_t*)(pb + ARRB + 16);
#pragma unroll
                for (int mt = 0; mt < 4; mt++) {
                    mma16(acc[mt][nt], ah[mt], bh0, bh1);
                    mma16(acc[mt][nt], ah[mt], bl0, bl1);
                    mma16(acc[mt][nt], al[mt], bh0, bh1);
                }
            }
        }
        __syncthreads();
    }

#pragma unroll
    for (int mt = 0; mt < 4; mt++) {
        int r = row0 + wm * 64 + mt * 16 + g;
#pragma unroll
        for (int nt = 0; nt < 4; nt++) {
            int c = col0 + wn * 32 + nt * 8 + ctg * 2;
            float b0 = bias[c], b1 = bias[c + 1];
            *(float2*)&C[(size_t)r * 1024 + c] =
                make_float2(acc[mt][nt][0] + b0, acc[mt][nt][1] + b1);
            *(float2*)&C[(size_t)(r + 8) * 1024 + c] =
                make_float2(acc[mt][nt][2] + b0, acc[mt][nt][3] + b1);
        }
    }
}

__global__ void mean_kernel(const float* __restrict__ q) {
    int idx = blockIdx.x * blockDim.x + threadIdx.x;
    int d = idx & (D_ - 1);
    int ba = idx / D_;
    int a = ba & (A_ - 1);
    int b = ba / A_;
    const float* base = q + ((size_t)(b * N_ + a * NA)) * D_ + d;
    float s = 0.f;
#pragma unroll 8
    for (int n = 0; n < NA; n++) s += base[(size_t)n * D_];
    g_agent_raw[idx] = s * (1.0f / NA);
}

// fp32 SGEMM, double-buffered (cp.async B, reg-staged A). Per-output FMA order
// is IDENTICAL to the R1 baseline kernel -> bit-identical results.
__global__ __launch_bounds__(256) void sgemm_bias(
    const float* __restrict__ A, const float* __restrict__ W,
    const float* __restrict__ bias, float* __restrict__ C, int M) {
    __shared__ float As[2][16][128];
    __shared__ float Bs[2][16][128];
    const int t = threadIdx.x;
    const int row0 = blockIdx.y * 128;
    const int col0 = blockIdx.x * 128;
    const int tr = t >> 4;
    const int tc = t & 15;
    const int ar0 = (t * 2) >> 2, ac0 = (t * 2) & 3;
    const int ar1 = (t * 2 + 1) >> 2, ac1 = (t * 2 + 1) & 3;
    const int br0 = (t * 2) >> 5, bc0 = (t * 2) & 31;
    const int br1 = (t * 2 + 1) >> 5, bc1 = (t * 2 + 1) & 31;
    const uint32_t sb0a = smem_u32(&Bs[0][br0][bc0 * 4]);
    const uint32_t sb0b = smem_u32(&Bs[0][br1][bc1 * 4]);
    const uint32_t sb1a = smem_u32(&Bs[1][br0][bc0 * 4]);
    const uint32_t sb1b = smem_u32(&Bs[1][br1][bc1 * 4]);

    float acc[8][8];
#pragma unroll
    for (int i = 0; i < 8; i++)
#pragma unroll
        for (int j = 0; j < 8; j++) acc[i][j] = 0.f;

    float4 av0, av1;
    const float4 z4 = make_float4(0.f, 0.f, 0.f, 0.f);

    // prologue: tile 0
    CP_ASYNC16(sb0a, &W[(size_t)br0 * 1024 + col0 + bc0 * 4]);
    CP_ASYNC16(sb0b, &W[(size_t)br1 * 1024 + col0 + bc1 * 4]);
    CP_COMMIT();
    av0 = (row0 + ar0 < M) ? *(const float4*)&A[(size_t)(row0 + ar0) * 1024 + ac0 * 4] : z4;
    av1 = (row0 + ar1 < M) ? *(const float4*)&A[(size_t)(row0 + ar1) * 1024 + ac1 * 4] : z4;
    As[0][ac0 * 4 + 0][ar0] = av0.x;
    As[0][ac0 * 4 + 1][ar0] = av0.y;
    As[0][ac0 * 4 + 2][ar0] = av0.z;
    As[0][ac0 * 4 + 3][ar0] = av0.w;
    As[0][ac1 * 4 + 0][ar1] = av1.x;
    As[0][ac1 * 4 + 1][ar1] = av1.y;
    As[0][ac1 * 4 + 2][ar1] = av1.z;
    As[0][ac1 * 4 + 3][ar1] = av1.w;
    CP_WAITN(0);
    __syncthreads();

    for (int k0 = 0; k0 < 1024; k0 += 16) {
        const int s = (k0 >> 4) & 1;
        const bool more = (k0 + 16 < 1024);
        if (more) {
            // prefetch next tile: B via cp.async into the other stage, A into regs
            CP_ASYNC16(s ? sb0a : sb1a, &W[(size_t)(k0 + 16 + br0) * 1024 + col0 + bc0 * 4]);
            CP_ASYNC16(s ? sb0b : sb1b, &W[(size_t)(k0 + 16 + br1) * 1024 + col0 + bc1 * 4]);
            CP_COMMIT();
            av0 = (row0 + ar0 < M)
                      ? *(const float4*)&A[(size_t)(row0 + ar0) * 1024 + k0 + 16 + ac0 * 4] : z4;
            av1 = (row0 + ar1 < M)
                      ? *(const float4*)&A[(size_t)(row0 + ar1) * 1024 + k0 + 16 + ac1 * 4] : z4;
        }
#pragma unroll
        for (int k = 0; k < 16; k++) {
            float ra[8], rb[8];
#pragma unroll
            for (int i = 0; i < 8; i++) ra[i] = As[s][k][tr * 8 + i];
#pragma unroll
            for (int j = 0; j < 8; j++) rb[j] = Bs[s][k][tc * 8 + j];
#pragma unroll
            for (int i = 0; i < 8; i++)
#pragma unroll
                for (int j = 0; j < 8; j++) acc[i][j] += ra[i] * rb[j];
        }
        if (more) {
            const int sn = s ^ 1;
            As[sn][ac0 * 4 + 0][ar0] = av0.x;
            As[sn][ac0 * 4 + 1][ar0] = av0.y;
            As[sn][ac0 * 4 + 2][ar0] = av0.z;
            As[sn][ac0 * 4 + 3][ar0] = av0.w;
            As[sn][ac1 * 4 + 0][ar1] = av1.x;
            As[sn][ac1 * 4 + 1][ar1] = av1.y;
            As[sn][ac1 * 4 + 2][ar1] = av1.z;
            As[sn][ac1 * 4 + 3][ar1] = av1.w;
            CP_WAITN(0);
            __syncthreads();
        }
    }

    float bv[8];
#pragma unroll
    for (int j = 0; j < 8; j++) bv[j] = bias[col0 + tc * 8 + j];
#pragma unroll
    for (int i = 0; i < 8; i++) {
        int r = row0 + tr * 8 + i;
        if (r < M) {
            float4 o0 = make_float4(acc[i][0] + bv[0], acc[i][1] + bv[1],
                                    acc[i][2] + bv[2], acc[i][3] + bv[3]);
            float4 o1 = make_float4(acc[i][4] + bv[4], acc[i][5] + bv[5],
                                    acc[i][6] + bv[6], acc[i][7] + bv[7]);
            *(float4*)&C[(size_t)r * 1024 + col0 + tc * 8 + 0] = o0;
            *(float4*)&C[(size_t)r * 1024 + col0 + tc * 8 + 4] = o1;
        }
    }
}

__global__ __launch_bounds__(256) void agent_scores_kernel() {
    int bh = blockIdx.x;
    int b = bh / H_, h = bh % H_;
    int t = threadIdx.x;
    int s = blockIdx.y * 256 + t;
    __shared__ float qs[A_][DH];
    for (int i = t; i < A_ * DH; i += 256) {
        int a = i / DH, d = i % DH;
        qs[a][d] = g_qa[(b * A_ + a) * D_ + h * DH + d];
    }
    __syncthreads();
    const float4* krow = (const float4*)&g_kc[((size_t)b * S_ + s) * D_ + h * DH];
    float acc[A_];
#pragma unroll
    for (int a = 0; a < A_; a++) acc[a] = 0.f;
#pragma unroll
    for (int d4 = 0; d4 < DH / 4; d4++) {
        float4 kv = krow[d4];
#pragma unroll
        for (int a = 0; a < A_; a++) {
            acc[a] += kv.x * qs[a][d4 * 4 + 0] + kv.y * qs[a][d4 * 4 + 1] +
                      kv.z * qs[a][d4 * 4 + 2] + kv.w * qs[a][d4 * 4 + 3];
        }
    }
#pragma unroll
    for (int a = 0; a < A_; a++)
        g_attn_agent[(((size_t)bh) * A_ + a) * S_ + s] = acc[a] * SCALE_;
}

__global__ __launch_bounds__(512) void topk_softmax_kernel(float* __restrict__ w_out) {
    __shared__ float v[S_];
    __shared__ float srt[S_];
    __shared__ float red[512];
    int row = blockIdx.x;
    int t = threadIdx.x;
    const float* src = g_attn_agent + (size_t)row * S_;
    for (int i = t; i < S_; i += 512) {
        float x = src[i];
        v[i] = x;
        srt[i] = x;
    }
    __syncthreads();
    for (int k = 2; k <= S_; k <<= 1) {
        for (int j = k >> 1; j > 0; j >>= 1) {
            for (int i = t; i < S_; i += 512) {
                int ixj = i ^ j;
                if (ixj > i) {
                    bool up = ((i & k) == 0);
                    float a = srt[i], b = srt[ixj];
                    if ((a > b) == up) { srt[i] = b; srt[ixj] = a; }
                }
            }
            __syncthreads();
        }
    }
    float thresh = srt[S_ - KKEEP];
    float mx = srt[S_ - 1];
    float lsum = 0.f;
    for (int i = t; i < S_; i += 512) {
        float x = v[i];
        float e = (x >= thresh) ? expf(x - mx) : 0.f;
        v[i] = e;
        lsum += e;
    }
    red[t] = lsum;
    __syncthreads();
    for (int o = 256; o > 0; o >>= 1) {
        if (t < o) red[t] += red[t + o];
        __syncthreads();
    }
    float inv = 1.f / red[0];
    float* dst = w_out + (size_t)row * S_;
    for (int i = t; i < S_; i += 512) dst[i] = v[i] * inv;
}

__global__ __launch_bounds__(512) void agent_out_kernel(const float* __restrict__ w) {
    int bh = blockIdx.x;
    int b = bh / H_, h = bh % H_;
    int t = threadIdx.x;
    int a = t / DH, d = t % DH;
    __shared__ float ws[A_][256];
    const float* wbase = w + ((size_t)bh * A_) * S_;
    const float* vbase = g_vc + ((size_t)b * S_) * D_ + h * DH;
    float acc = 0.f;
    for (int s0 = 0; s0 < S_; s0 += 256) {
        for (int i = t; i < A_ * 256; i += 512) {
            int aa = i >> 8, ss = i & 255;
            ws[aa][ss] = wbase[(size_t)aa * S_ + s0 + ss];
        }
        __syncthreads();
#pragma unroll 8
        for (int ss = 0; ss < 256; ss++)
            acc += ws[a][ss] * vbase[(size_t)(s0 + ss) * D_ + d];
        __syncthreads();
    }
    g_agent_out[(b * A_ + a) * D_ + h * DH + d] = acc;
}

// writes attn_final + bf16 hi/lo split of outpre into g_ah/g_al
__global__ __launch_bounds__(256) void final_attn_kernel(float* __restrict__ attn_out) {
    int bh = blockIdx.x;
    int b = bh / H_, h = bh % H_;
    int t = threadIdx.x;
    int n = blockIdx.y * 256 + t;
    __shared__ float ks[A_][DH], vs[A_][DH];
    for (int i = t; i < A_ * DH; i += 256) {
        int a = i / DH, d = i % DH;
        ks[a][d] = g_ka[(b * A_ + a) * D_ + h * DH + d];
        vs[a][d] = g_va[(b * A_ + a) * D_ + h * DH + d];
    }
    __syncthreads();
    const float4* qrow = (const float4*)&g_qo[((size_t)b * N_ + n) * D_ + h * DH];
    float sc[A_];
#pragma unroll
    for (int a = 0; a < A_; a++) sc[a] = 0.f;
#pragma unroll
    for (int d4 = 0; d4 < DH / 4; d4++) {
        float4 q = qrow[d4];
#pragma unroll
        for (int a = 0; a < A_; a++) {
            sc[a] += q.x * ks[a][d4 * 4 + 0] + q.y * ks[a][d4 * 4 + 1] +
                     q.z * ks[a][d4 * 4 + 2] + q.w * ks[a][d4 * 4 + 3];
        }
    }
    float mx = -1e30f;
#pragma unroll
    for (int a = 0; a < A_; a++) {
        sc[a] *= SCALE_;
        mx = fmaxf(mx, sc[a]);
    }
    float sum = 0.f;
#pragma unroll
    for (int a = 0; a < A_; a++) {
        sc[a] = expf(sc[a] - mx);
        sum += sc[a];
    }
    float inv = 1.f / sum;
#pragma unroll
    for (int a = 0; a < A_; a++) sc[a] *= inv;
    float* ao = attn_out + (((size_t)bh) * N_ + n) * A_;
#pragma unroll
    for (int a = 0; a < A_; a++) ao[a] = sc[a];
    const size_t obase = ((size_t)b * N_ + n) * D_ + h * DH;
#pragma unroll
    for (int d4 = 0; d4 < DH / 4; d4++) {
        float4 o = make_float4(0.f, 0.f, 0.f, 0.f);
#pragma unroll
        for (int a = 0; a < A_; a++) {
            float w = sc[a];
            o.x += w * vs[a][d4 * 4 + 0];
            o.y += w * vs[a][d4 * 4 + 1];
            o.z += w * vs[a][d4 * 4 + 2];
            o.w += w * vs[a][d4 * 4 + 3];
        }
        __nv_bfloat16 h0, l0, h1, l1, h2, l2, h3, l3;
        bf16_split(o.x, h0, l0);
        bf16_split(o.y, h1, l1);
        bf16_split(o.z, h2, l2);
        bf16_split(o.w, h3, l3);
        *(uint2*)(g_ah + obase + d4 * 4) = make_uint2(pk2(h0, h1), pk2(h2, h3));
        *(uint2*)(g_al + obase + d4 * 4) = make_uint2(pk2(l0, l1), pk2(l2, l3));
    }
}

extern "C" void kernel_launch(void* const* d_in, const int* in_sizes, int n_in,
                              void* d_out, int out_size) {
    const float* query = (const float*)d_in[0];
    const float* key = (const float*)d_in[1];
    const float* value = (const float*)d_in[2];
    const float* W_agent = (const float*)d_in[3];
    const float* b_agent = (const float*)d_in[4];
    const float* W_qa = (const float*)d_in[5];
    const float* b_qa = (const float*)d_in[6];
    const float* W_kc = (const float*)d_in[7];
    const float* b_kc = (const float*)d_in[8];
    const float* W_vc = (const float*)d_in[9];
    const float* b_vc = (const float*)d_in[10];
    const float* W_qo = (const float*)d_in[11];
    const float* b_qo = (const float*)d_in[12];
    const float* W_ka = (const float*)d_in[13];
    const float* b_ka = (const float*)d_in[14];
    const float* W_va = (const float*)d_in[15];
    const float* b_va = (const float*)d_in[16];
    const float* W_proj = (const float*)d_in[17];
    const float* b_proj = (const float*)d_in[18];

    float* out0 = (float*)d_out;
    float* out_attn_final = out0 + (size_t)B_ * N_ * D_;
    float* out_attn_agent_w = out_attn_final + (size_t)B_ * H_ * N_ * A_;

    float *p_raw, *p_tok, *p_qa, *p_kc, *p_vc, *p_qo, *p_ka, *p_va, *p_aout;
    __nv_bfloat16 *p_ah, *p_al, *p_ah2, *p_al2, *p_bh1, *p_bl1, *p_bh2, *p_bl2, *p_bh3, *p_bl3;
    cudaGetSymbolAddress((void**)&p_raw, g_agent_raw);
    cudaGetSymbolAddress((void**)&p_tok, g_agent_tok);
    cudaGetSymbolAddress((void**)&p_qa, g_qa);
    cudaGetSymbolAddress((void**)&p_kc, g_kc);
    cudaGetSymbolAddress((void**)&p_vc, g_vc);
    cudaGetSymbolAddress((void**)&p_qo, g_qo);
    cudaGetSymbolAddress((void**)&p_ka, g_ka);
    cudaGetSymbolAddress((void**)&p_va, g_va);
    cudaGetSymbolAddress((void**)&p_aout, g_agent_out);
    cudaGetSymbolAddress((void**)&p_ah, g_ah);
    cudaGetSymbolAddress((void**)&p_al, g_al);
    cudaGetSymbolAddress((void**)&p_ah2, g_ah2);
    cudaGetSymbolAddress((void**)&p_al2, g_al2);
    cudaGetSymbolAddress((void**)&p_bh1, g_bh1);
    cudaGetSymbolAddress((void**)&p_bl1, g_bl1);
    cudaGetSymbolAddress((void**)&p_bh2, g_bh2);
    cudaGetSymbolAddress((void**)&p_bl2, g_bl2);
    cudaGetSymbolAddress((void**)&p_bh3, g_bh3);
    cudaGetSymbolAddress((void**)&p_bl3, g_bl3);

    static cudaStream_t s1 = nullptr, s2 = nullptr;
    static cudaEvent_t evRoot = nullptr, evVC = nullptr, evQO = nullptr;
    if (!s1) {
        cudaStreamCreateWithFlags(&s1, cudaStreamNonBlocking);
        cudaStreamCreateWithFlags(&s2, cudaStreamNonBlocking);
        cudaEventCreateWithFlags(&evRoot, cudaEventDisableTiming);
        cudaEventCreateWithFlags(&evVC, cudaEventDisableTiming);
        cudaEventCreateWithFlags(&evQO, cudaEventDisableTiming);
        cudaFuncSetAttribute(mma_gemm_kernel,
                             cudaFuncAttributeMaxDynamicSharedMemorySize, SMEM_MMA);
    }

    const int MBIG = B_ * N_;   // 32768
    const int MSM = B_ * A_;    // 64
    dim3 gsm(8, 1);
    dim3 gbig(8, MBIG / 128);
    dim3 gmma(1024 / BN, MBIG / BM);       // (8, 256)
    dim3 gsw(32, 32);
    dim3 bsw(32, 8);
    const int SA_BLK = (MBIG * D_ / 8) / 256;   // 16384

    // ---- fork side streams ----
    cudaEventRecord(evRoot, 0);
    cudaStreamWaitEvent(s1, evRoot, 0);
    cudaStreamWaitEvent(s2, evRoot, 0);

    // s1: v_c pipeline
    split_w_bf16<<<gsw, bsw, 0, s1>>>(W_vc, p_bh1, p_bl1);
    split_a_bf16<<<SA_BLK, 256, 0, s1>>>(value, p_ah, p_al);
    mma_gemm_kernel<<<gmma, 256, SMEM_MMA, s1>>>(p_ah, p_al, p_bh1, p_bl1, b_vc, p_vc);
    cudaEventRecord(evVC, s1);

    // s2: q_o pipeline + proj weight split
    split_w_bf16<<<gsw, bsw, 0, s2>>>(W_qo, p_bh2, p_bl2);
    split_a_bf16<<<SA_BLK, 256, 0, s2>>>(query, p_ah2, p_al2);
    mma_gemm_kernel<<<gmma, 256, SMEM_MMA, s2>>>(p_ah2, p_al2, p_bh2, p_bl2, b_qo, p_qo);
    split_w_bf16<<<gsw, bsw, 0, s2>>>(W_proj, p_bh3, p_bl3);
    cudaEventRecord(evQO, s2);

    // s0: flip-determining path (bit-identical numerics)
    mean_kernel<<<(B_ * A_ * D_) / 256, 256>>>(query);
    sgemm_bias<<<gsm, 256>>>(p_raw, W_agent, b_agent, p_tok, MSM);
    sgemm_bias<<<gsm, 256>>>(p_tok, W_qa, b_qa, p_qa, MSM);
    sgemm_bias<<<gbig, 256>>>(key, W_kc, b_kc, p_kc, MBIG);
    agent_scores_kernel<<<dim3(B_ * H_, S_ / 256), 256>>>();
    topk_softmax_kernel<<<B_ * H_ * A_, 512>>>(out_attn_agent_w);

    cudaStreamWaitEvent(0, evVC, 0);
    agent_out_kernel<<<B_ * H_, 512>>>(out_attn_agent_w);
    sgemm_bias<<<gsm, 256>>>(p_aout, W_ka, b_ka, p_ka, MSM);
    sgemm_bias<<<gsm, 256>>>(p_aout, W_va, b_va, p_va, MSM);

    cudaStreamWaitEvent(0, evQO, 0);
    final_attn_kernel<<<dim3(B_ * H_, N_ / 256), 256>>>(out_attn_final);
    mma_gemm_kernel<<<gmma, 256, SMEM_MMA>>>(p_ah, p_al, p_bh3, p_bl3, b_proj, out0);
}

// round 14
// speedup vs baseline: 1.4398x; 1.4398x over previous
#include <cuda_runtime.h>
#include <cuda_bf16.h>
#include <cstddef>
#include <cstdint>

#define B_ 8
#define N_ 4096
#define S_ 4096
#define D_ 1024
#define H_ 16
#define A_ 8
#define DH 64
#define NA 512
#define KKEEP 2048
#define SCALE_ 0.125f

// bf16 mma tiling: BM=128, BN=128, BK=32 (2 x k16 steps), pitch 80B rows
#define BM 128
#define BN 128
#define ARRB 10240              // bytes per array: 128 rows * 80
#define STAGE_B 40960           // Ah+Al+Bh+Bl
#define SMEM_MMA 81920          // 2 stages

__device__ float g_kc[(size_t)B_ * S_ * D_];
__device__ float g_vc[(size_t)B_ * S_ * D_];
__device__ float g_qo[(size_t)B_ * N_ * D_];
__device__ float g_attn_agent[(size_t)B_ * H_ * A_ * S_];
__device__ float g_agent_raw[B_ * A_ * D_];
__device__ float g_agent_tok[B_ * A_ * D_];
__device__ float g_qa[B_ * A_ * D_];
__device__ float g_ka[B_ * A_ * D_];
__device__ float g_va[B_ * A_ * D_];
__device__ float g_agent_out[B_ * A_ * D_];
// bf16 split operands
__device__ __nv_bfloat16 g_ah[(size_t)B_ * N_ * D_];
__device__ __nv_bfloat16 g_al[(size_t)B_ * N_ * D_];
__device__ __nv_bfloat16 g_ah2[(size_t)B_ * N_ * D_];
__device__ __nv_bfloat16 g_al2[(size_t)B_ * N_ * D_];
__device__ __nv_bfloat16 g_bh1[(size_t)D_ * D_], g_bl1[(size_t)D_ * D_];
__device__ __nv_bfloat16 g_bh2[(size_t)D_ * D_], g_bl2[(size_t)D_ * D_];
__device__ __nv_bfloat16 g_bh3[(size_t)D_ * D_], g_bl3[(size_t)D_ * D_];

__device__ __forceinline__ uint32_t smem_u32(const void* p) {
    uint32_t a;
    asm("{ .reg .u64 t; cvta.to.shared.u64 t, %1; cvt.u32.u64 %0, t; }" : "=r"(a) : "l"(p));
    return a;
}
#define CP_ASYNC16(dst, src) \
    asm volatile("cp.async.cg.shared.global [%0], [%1], 16;" :: "r"(dst), "l"(src) : "memory")
#define CP_COMMIT() asm volatile("cp.async.commit_group;" ::: "memory")
#define CP_WAITN(n) asm volatile("cp.async.wait_group %0;" :: "n"(n) : "memory")

__device__ __forceinline__ void mma16(float* d, const uint32_t* a, uint32_t b0, uint32_t b1) {
    asm volatile(
        "mma.sync.aligned.m16n8k16.row.col.f32.bf16.bf16.f32 "
        "{%0,%1,%2,%3}, {%4,%5,%6,%7}, {%8,%9}, {%0,%1,%2,%3};"
        : "+f"(d[0]), "+f"(d[1]), "+f"(d[2]), "+f"(d[3])
        : "r"(a[0]), "r"(a[1]), "r"(a[2]), "r"(a[3]), "r"(b0), "r"(b1));
}

__device__ __forceinline__ void bf16_split(float v, __nv_bfloat16& h, __nv_bfloat16& l) {
    h = __float2bfloat16_rn(v);
    l = __float2bfloat16_rn(v - __bfloat162float(h));
}
__device__ __forceinline__ uint32_t pk2(__nv_bfloat16 a, __nv_bfloat16 b) {
    return (uint32_t)__bfloat16_as_ushort(a) | ((uint32_t)__bfloat16_as_ushort(b) << 16);
}

// A[M,1024] fp32 -> bf16 hi/lo (row-major). 8 floats/thread.
__global__ __launch_bounds__(256) void split_a_bf16(const float* __restrict__ a,
                                                    __nv_bfloat16* __restrict__ hi,
                                                    __nv_bfloat16* __restrict__ lo) {
    size_t i = (size_t)blockIdx.x * 256 + threadIdx.x;
    const float4* s4 = (const float4*)a + i * 2;
    float4 x = s4[0], y = s4[1];
    float v[8] = {x.x, x.y, x.z, x.w, y.x, y.y, y.z, y.w};
    uint32_t hp[4], lp[4];
#pragma unroll
    for (int j = 0; j < 4; j++) {
        __nv_bfloat16 h0, l0, h1, l1;
        bf16_split(v[2 * j], h0, l0);
        bf16_split(v[2 * j + 1], h1, l1);
        hp[j] = pk2(h0, h1);
        lp[j] = pk2(l0, l1);
    }
    *(uint4*)(hi + i * 8) = make_uint4(hp[0], hp[1], hp[2], hp[3]);
    *(uint4*)(lo + i * 8) = make_uint4(lp[0], lp[1], lp[2], lp[3]);
}

// W[k][n] fp32 -> bf16 hi/lo transposed [n][k]
__global__ __launch_bounds__(256) void split_w_bf16(const float* __restrict__ w,
                                                    __nv_bfloat16* __restrict__ hi,
                                                    __nv_bfloat16* __restrict__ lo) {
    __shared__ float t[32][33];
    int k0 = blockIdx.y * 32, n0 = blockIdx.x * 32;
    int tx = threadIdx.x, ty = threadIdx.y;
    for (int i = ty; i < 32; i += 8)
        t[i][tx] = w[(size_t)(k0 + i) * 1024 + n0 + tx];
    __syncthreads();
    for (int i = ty; i < 32; i += 8) {
        __nv_bfloat16 h, l;
        bf16_split(t[tx][i], h, l);
        hi[(size_t)(n0 + i) * 1024 + k0 + tx] = h;
        lo[(size_t)(n0 + i) * 1024 + k0 + tx] = l;
    }
}

// C[M,1024] = (Ah+Al)@(Bh+Bl)^T + bias, 3xBF16 m16n8k16. grid=(8, M/128), 2 CTA/SM
__global__ __launch_bounds__(256, 2) void mma_gemm_kernel(
    const __nv_bfloat16* __restrict__ gAh, const __nv_bfloat16* __restrict__ gAl,
    const __nv_bfloat16* __restrict__ gBh, const __nv_bfloat16* __restrict__ gBl,
    const float* __restrict__ bias, float* __restrict__ C) {
    extern __shared__ __align__(16) char smem[];
    const int tid = threadIdx.x;
    const int row0 = blockIdx.y * BM;
    const int col0 = blockIdx.x * BN;
    const int w = tid >> 5;
    const int lane = tid & 31;
    const int wm = w >> 2;
    const int wn = w & 3;
    const int g = lane >> 2;
    const int ctg = lane & 3;

    float acc[4][4][4];
#pragma unroll
    for (int mt = 0; mt < 4; mt++)
#pragma unroll
        for (int nt = 0; nt < 4; nt++)
#pragma unroll
            for (int r = 0; r < 4; r++) acc[mt][nt][r] = 0.f;

    auto load_stage = [&](int s, int kt) {
        char* st = smem + s * STAGE_B;
        const int k0 = kt * 32;
#pragma unroll
        for (int j = 0; j < 2; j++) {
            int cid = j * 256 + tid;
            int r = cid >> 2, c = cid & 3;
            uint32_t da = smem_u32(st + r * 80 + c * 16);
            size_t ga = (size_t)(row0 + r) * 1024 + k0 + c * 8;
            CP_ASYNC16(da, gAh + ga);
            CP_ASYNC16(da + ARRB, gAl + ga);
            uint32_t db = smem_u32(st + 2 * ARRB + r * 80 + c * 16);
            size_t gb = (size_t)(col0 + r) * 1024 + k0 + c * 8;
            CP_ASYNC16(db, gBh + gb);
            CP_ASYNC16(db + ARRB, gBl + gb);
        }
        CP_COMMIT();
    };

    load_stage(0, 0);

    for (int kt = 0; kt < 32; kt++) {
        if (kt + 1 < 32) {
            load_stage((kt + 1) & 1, kt + 1);
            CP_WAITN(1);
        } else {
            CP_WAITN(0);
        }
        __syncthreads();
        const char* st = smem + (kt & 1) * STAGE_B;
#pragma unroll
        for (int ks = 0; ks < 2; ks++) {
            const int ko = ks * 32;
            uint32_t ah[4][4], al[4][4];
#pragma unroll
            for (int mt = 0; mt < 4; mt++) {
                int r = wm * 64 + mt * 16 + g;
                const char* pa = st + r * 80 + ko + ctg * 4;
                ah[mt][0] = *(const uint32_t*)(pa);
                ah[mt][1] = *(const uint32_t*)(pa + 8 * 80);
                ah[mt][2] = *(const uint32_t*)(pa + 16);
                ah[mt][3] = *(const uint32_t*)(pa + 8 * 80 + 16);
                const char* pl = pa + ARRB;
                al[mt][0] = *(const uint32_t*)(pl);
                al[mt][1] = *(const uint32_t*)(pl + 8 * 80);
                al[mt][2] = *(const uint32_t*)(pl + 16);
                al[mt][3] = *(const uint32_t*)(pl + 8 * 80 + 16);
            }
#pragma unroll
            for (int nt = 0; nt < 4; nt++) {
                int n = wn * 32 + nt * 8 + g;
                const char* pb = st + 2 * ARRB + n * 80 + ko + ctg * 4;
                uint32_t bh0 = *(const uint32_t*)(pb);
                uint32_t bh1 = *(const uint32_t*)(pb + 16);
                uint32_t bl0 = *(const uint32_t*)(pb + ARRB);
                uint32_t bl1 = *(const uint32_t*)(pb + ARRB + 16);
#pragma unroll
                for (int mt = 0; mt < 4; mt++) {
                    mma16(acc[mt][nt], ah[mt], bh0, bh1);
                    mma16(acc[mt][nt], ah[mt], bl0, bl1);
                    mma16(acc[mt][nt], al[mt], bh0, bh1);
                }
            }
        }
        __syncthreads();
    }

#pragma unroll
    for (int mt = 0; mt < 4; mt++) {
        int r = row0 + wm * 64 + mt * 16 + g;
#pragma unroll
        for (int nt = 0; nt < 4; nt++) {
            int c = col0 + wn * 32 + nt * 8 + ctg * 2;
            float b0 = bias[c], b1 = bias[c + 1];
            *(float2*)&C[(size_t)r * 1024 + c] =
                make_float2(acc[mt][nt][0] + b0, acc[mt][nt][1] + b1);
            *(float2*)&C[(size_t)(r + 8) * 1024 + c] =
                make_float2(acc[mt][nt][2] + b0, acc[mt][nt][3] + b1);
        }
    }
}

__global__ void mean_kernel(const float* __restrict__ q) {
    int idx = blockIdx.x * blockDim.x + threadIdx.x;
    int d = idx & (D_ - 1);
    int ba = idx / D_;
    int a = ba & (A_ - 1);
    int b = ba / A_;
    const float* base = q + ((size_t)(b * N_ + a * NA)) * D_ + d;
    float s = 0.f;
#pragma unroll 8
    for (int n = 0; n < NA; n++) s += base[(size_t)n * D_];
    g_agent_raw[idx] = s * (1.0f / NA);
}

// fp32 SGEMM: single smem buffer, register-prefetch of the next K-tile.
// Inner compute loop (FMA order per output) is textually IDENTICAL to the R1
// baseline -> bit-identical results -> identical top-k flips.
__global__ __launch_bounds__(256, 2) void sgemm_bias(
    const float* __restrict__ A, const float* __restrict__ W,
    const float* __restrict__ bias, float* __restrict__ C, int M) {
    __shared__ float As[16][128];
    __shared__ float Bs[16][128];
    const int t = threadIdx.x;
    const int row0 = blockIdx.y * 128;
    const int col0 = blockIdx.x * 128;
    const int tr = t >> 4;
    const int tc = t & 15;
    const int ar0 = (t * 2) >> 2, ac0 = (t * 2) & 3;
    const int ar1 = (t * 2 + 1) >> 2, ac1 = (t * 2 + 1) & 3;
    const int br0 = (t * 2) >> 5, bc0 = (t * 2) & 31;
    const int br1 = (t * 2 + 1) >> 5, bc1 = (t * 2 + 1) & 31;
    const float4 z4 = make_float4(0.f, 0.f, 0.f, 0.f);

    float acc[8][8];
#pragma unroll
    for (int i = 0; i < 8; i++)
#pragma unroll
        for (int j = 0; j < 8; j++) acc[i][j] = 0.f;

    // tile 0 load (same addresses as R1 baseline)
    float4 av0 = (row0 + ar0 < M) ? *(const float4*)&A[(size_t)(row0 + ar0) * 1024 + ac0 * 4] : z4;
    float4 av1 = (row0 + ar1 < M) ? *(const float4*)&A[(size_t)(row0 + ar1) * 1024 + ac1 * 4] : z4;
    float4 bv0 = *(const float4*)&W[(size_t)br0 * 1024 + col0 + bc0 * 4];
    float4 bv1 = *(const float4*)&W[(size_t)br1 * 1024 + col0 + bc1 * 4];
    As[ac0 * 4 + 0][ar0] = av0.x;
    As[ac0 * 4 + 1][ar0] = av0.y;
    As[ac0 * 4 + 2][ar0] = av0.z;
    As[ac0 * 4 + 3][ar0] = av0.w;
    As[ac1 * 4 + 0][ar1] = av1.x;
    As[ac1 * 4 + 1][ar1] = av1.y;
    As[ac1 * 4 + 2][ar1] = av1.z;
    As[ac1 * 4 + 3][ar1] = av1.w;
    *(float4*)&Bs[br0][bc0 * 4] = bv0;
    *(float4*)&Bs[br1][bc1 * 4] = bv1;
    __syncthreads();

    for (int k0 = 0; k0 < 1024; k0 += 16) {
        const bool more = (k0 + 16 < 1024);
        if (more) {
            // prefetch next tile into registers; latency hides under compute
            av0 = (row0 + ar0 < M)
                      ? *(const float4*)&A[(size_t)(row0 + ar0) * 1024 + k0 + 16 + ac0 * 4] : z4;
            av1 = (row0 + ar1 < M)
                      ? *(const float4*)&A[(size_t)(row0 + ar1) * 1024 + k0 + 16 + ac1 * 4] : z4;
            bv0 = *(const float4*)&W[(size_t)(k0 + 16 + br0) * 1024 + col0 + bc0 * 4];
            bv1 = *(const float4*)&W[(size_t)(k0 + 16 + br1) * 1024 + col0 + bc1 * 4];
        }
#pragma unroll
        for (int k = 0; k < 16; k++) {
            float ra[8], rb[8];
#pragma unroll
            for (int i = 0; i < 8; i++) ra[i] = As[k][tr * 8 + i];
#pragma unroll
            for (int j = 0; j < 8; j++) rb[j] = Bs[k][tc * 8 + j];
#pragma unroll
            for (int i = 0; i < 8; i++)
#pragma unroll
                for (int j = 0; j < 8; j++) acc[i][j] += ra[i] * rb[j];
        }
        if (more) {
            __syncthreads();
            As[ac0 * 4 + 0][ar0] = av0.x;
            As[ac0 * 4 + 1][ar0] = av0.y;
            As[ac0 * 4 + 2][ar0] = av0.z;
            As[ac0 * 4 + 3][ar0] = av0.w;
            As[ac1 * 4 + 0][ar1] = av1.x;
            As[ac1 * 4 + 1][ar1] = av1.y;
            As[ac1 * 4 + 2][ar1] = av1.z;
            As[ac1 * 4 + 3][ar1] = av1.w;
            *(float4*)&Bs[br0][bc0 * 4] = bv0;
            *(float4*)&Bs[br1][bc1 * 4] = bv1;
            __syncthreads();
        }
    }

    float bv[8];
#pragma unroll
    for (int j = 0; j < 8; j++) bv[j] = bias[col0 + tc * 8 + j];
#pragma unroll
    for (int i = 0; i < 8; i++) {
        int r = row0 + tr * 8 + i;
        if (r < M) {
            float4 o0 = make_float4(acc[i][0] + bv[0], acc[i][1] + bv[1],
                                    acc[i][2] + bv[2], acc[i][3] + bv[3]);
            float4 o1 = make_float4(acc[i][4] + bv[4], acc[i][5] + bv[5],
                                    acc[i][6] + bv[6], acc[i][7] + bv[7]);
            *(float4*)&C[(size_t)r * 1024 + col0 + tc * 8 + 0] = o0;
            *(float4*)&C[(size_t)r * 1024 + col0 + tc * 8 + 4] = o1;
        }
    }
}

__global__ __launch_bounds__(256) void agent_scores_kernel() {
    int bh = blockIdx.x;
    int b = bh / H_, h = bh % H_;
    int t = threadIdx.x;
    int s = blockIdx.y * 256 + t;
    __shared__ float qs[A_][DH];
    for (int i = t; i < A_ * DH; i += 256) {
        int a = i / DH, d = i % DH;
        qs[a][d] = g_qa[(b * A_ + a) * D_ + h * DH + d];
    }
    __syncthreads();
    const float4* krow = (const float4*)&g_kc[((size_t)b * S_ + s) * D_ + h * DH];
    float acc[A_];
#pragma unroll
    for (int a = 0; a < A_; a++) acc[a] = 0.f;
#pragma unroll
    for (int d4 = 0; d4 < DH / 4; d4++) {
        float4 kv = krow[d4];
#pragma unroll
        for (int a = 0; a < A_; a++) {
            acc[a] += kv.x * qs[a][d4 * 4 + 0] + kv.y * qs[a][d4 * 4 + 1] +
                      kv.z * qs[a][d4 * 4 + 2] + kv.w * qs[a][d4 * 4 + 3];
        }
    }
#pragma unroll
    for (int a = 0; a < A_; a++)
        g_attn_agent[(((size_t)bh) * A_ + a) * S_ + s] = acc[a] * SCALE_;
}

__global__ __launch_bounds__(512) void topk_softmax_kernel(float* __restrict__ w_out) {
    __shared__ float v[S_];
    __shared__ float srt[S_];
    __shared__ float red[512];
    int row = blockIdx.x;
    int t = threadIdx.x;
    const float* src = g_attn_agent + (size_t)row * S_;
    for (int i = t; i < S_; i += 512) {
        float x = src[i];
        v[i] = x;
        srt[i] = x;
    }
    __syncthreads();
    for (int k = 2; k <= S_; k <<= 1) {
        for (int j = k >> 1; j > 0; j >>= 1) {
            for (int i = t; i < S_; i += 512) {
                int ixj = i ^ j;
                if (ixj > i) {
                    bool up = ((i & k) == 0);
                    float a = srt[i], b = srt[ixj];
                    if ((a > b) == up) { srt[i] = b; srt[ixj] = a; }
                }
            }
            __syncthreads();
        }
    }
    float thresh = srt[S_ - KKEEP];
    float mx = srt[S_ - 1];
    float lsum = 0.f;
    for (int i = t; i < S_; i += 512) {
        float x = v[i];
        float e = (x >= thresh) ? expf(x - mx) : 0.f;
        v[i] = e;
        lsum += e;
    }
    red[t] = lsum;
    __syncthreads();
    for (int o = 256; o > 0; o >>= 1) {
        if (t < o) red[t] += red[t + o];
        __syncthreads();
    }
    float inv = 1.f / red[0];
    float* dst = w_out + (size_t)row * S_;
    for (int i = t; i < S_; i += 512) dst[i] = v[i] * inv;
}

__global__ __launch_bounds__(512) void agent_out_kernel(const float* __restrict__ w) {
    int bh = blockIdx.x;
    int b = bh / H_, h = bh % H_;
    int t = threadIdx.x;
    int a = t / DH, d = t % DH;
    __shared__ float ws[A_][256];
    const float* wbase = w + ((size_t)bh * A_) * S_;
    const float* vbase = g_vc + ((size_t)b * S_) * D_ + h * DH;
    float acc = 0.f;
    for (int s0 = 0; s0 < S_; s0 += 256) {
        for (int i = t; i < A_ * 256; i += 512) {
            int aa = i >> 8, ss = i & 255;
            ws[aa][ss] = wbase[(size_t)aa * S_ + s0 + ss];
        }
        __syncthreads();
#pragma unroll 8
        for (int ss = 0; ss < 256; ss++)
            acc += ws[a][ss] * vbase[(size_t)(s0 + ss) * D_ + d];
        __syncthreads();
    }
    g_agent_out[(b * A_ + a) * D_ + h * DH + d] = acc;
}

// writes attn_final + bf16 hi/lo split of outpre into g_ah/g_al
__global__ __launch_bounds__(256) void final_attn_kernel(float* __restrict__ attn_out) {
    int bh = blockIdx.x;
    int b = bh / H_, h = bh % H_;
    int t = threadIdx.x;
    int n = blockIdx.y * 256 + t;
    __shared__ float ks[A_][DH], vs[A_][DH];
    for (int i = t; i < A_ * DH; i += 256) {
        int a = i / DH, d = i % DH;
        ks[a][d] = g_ka[(b * A_ + a) * D_ + h * DH + d];
        vs[a][d] = g_va[(b * A_ + a) * D_ + h * DH + d];
    }
    __syncthreads();
    const float4* qrow = (const float4*)&g_qo[((size_t)b * N_ + n) * D_ + h * DH];
    float sc[A_];
#pragma unroll
    for (int a = 0; a < A_; a++) sc[a] = 0.f;
#pragma unroll
    for (int d4 = 0; d4 < DH / 4; d4++) {
        float4 q = qrow[d4];
#pragma unroll
        for (int a = 0; a < A_; a++) {
            sc[a] += q.x * ks[a][d4 * 4 + 0] + q.y * ks[a][d4 * 4 + 1] +
                     q.z * ks[a][d4 * 4 + 2] + q.w * ks[a][d4 * 4 + 3];
        }
    }
    float mx = -1e30f;
#pragma unroll
    for (int a = 0; a < A_; a++) {
        sc[a] *= SCALE_;
        mx = fmaxf(mx, sc[a]);
    }
    float sum = 0.f;
#pragma unroll
    for (int a = 0; a < A_; a++) {
        sc[a] = expf(sc[a] - mx);
        sum += sc[a];
    }
    float inv = 1.f / sum;
#pragma unroll
    for (int a = 0; a < A_; a++) sc[a] *= inv;
    float* ao = attn_out + (((size_t)bh) * N_ + n) * A_;
#pragma unroll
    for (int a = 0; a < A_; a++) ao[a] = sc[a];
    const size_t obase = ((size_t)b * N_ + n) * D_ + h * DH;
#pragma unroll
    for (int d4 = 0; d4 < DH / 4; d4++) {
        float4 o = make_float4(0.f, 0.f, 0.f, 0.f);
#pragma unroll
        for (int a = 0; a < A_; a++) {
            float w = sc[a];
            o.x += w * vs[a][d4 * 4 + 0];
            o.y += w * vs[a][d4 * 4 + 1];
            o.z += w * vs[a][d4 * 4 + 2];
            o.w += w * vs[a][d4 * 4 + 3];
        }
        __nv_bfloat16 h0, l0, h1, l1, h2, l2, h3, l3;
        bf16_split(o.x, h0, l0);
        bf16_split(o.y, h1, l1);
        bf16_split(o.z, h2, l2);
        bf16_split(o.w, h3, l3);
        *(uint2*)(g_ah + obase + d4 * 4) = make_uint2(pk2(h0, h1), pk2(h2, h3));
        *(uint2*)(g_al + obase + d4 * 4) = make_uint2(pk2(l0, l1), pk2(l2, l3));
    }
}

extern "C" void kernel_launch(void* const* d_in, const int* in_sizes, int n_in,
                              void* d_out, int out_size) {
    const float* query = (const float*)d_in[0];
    const float* key = (const float*)d_in[1];
    const float* value = (const float*)d_in[2];
    const float* W_agent = (const float*)d_in[3];
    const float* b_agent = (const float*)d_in[4];
    const float* W_qa = (const float*)d_in[5];
    const float* b_qa = (const float*)d_in[6];
    const float* W_kc = (const float*)d_in[7];
    const float* b_kc = (const float*)d_in[8];
    const float* W_vc = (const float*)d_in[9];
    const float* b_vc = (const float*)d_in[10];
    const float* W_qo = (const float*)d_in[11];
    const float* b_qo = (const float*)d_in[12];
    const float* W_ka = (const float*)d_in[13];
    const float* b_ka = (const float*)d_in[14];
    const float* W_va = (const float*)d_in[15];
    const float* b_va = (const float*)d_in[16];
    const float* W_proj = (const float*)d_in[17];
    const float* b_proj = (const float*)d_in[18];

    float* out0 = (float*)d_out;
    float* out_attn_final = out0 + (size_t)B_ * N_ * D_;
    float* out_attn_agent_w = out_attn_final + (size_t)B_ * H_ * N_ * A_;

    float *p_raw, *p_tok, *p_qa, *p_kc, *p_vc, *p_qo, *p_ka, *p_va, *p_aout;
    __nv_bfloat16 *p_ah, *p_al, *p_ah2, *p_al2, *p_bh1, *p_bl1, *p_bh2, *p_bl2, *p_bh3, *p_bl3;
    cudaGetSymbolAddress((void**)&p_raw, g_agent_raw);
    cudaGetSymbolAddress((void**)&p_tok, g_agent_tok);
    cudaGetSymbolAddress((void**)&p_qa, g_qa);
    cudaGetSymbolAddress((void**)&p_kc, g_kc);
    cudaGetSymbolAddress((void**)&p_vc, g_vc);
    cudaGetSymbolAddress((void**)&p_qo, g_qo);
    cudaGetSymbolAddress((void**)&p_ka, g_ka);
    cudaGetSymbolAddress((void**)&p_va, g_va);
    cudaGetSymbolAddress((void**)&p_aout, g_agent_out);
    cudaGetSymbolAddress((void**)&p_ah, g_ah);
    cudaGetSymbolAddress((void**)&p_al, g_al);
    cudaGetSymbolAddress((void**)&p_ah2, g_ah2);
    cudaGetSymbolAddress((void**)&p_al2, g_al2);
    cudaGetSymbolAddress((void**)&p_bh1, g_bh1);
    cudaGetSymbolAddress((void**)&p_bl1, g_bl1);
    cudaGetSymbolAddress((void**)&p_bh2, g_bh2);
    cudaGetSymbolAddress((void**)&p_bl2, g_bl2);
    cudaGetSymbolAddress((void**)&p_bh3, g_bh3);
    cudaGetSymbolAddress((void**)&p_bl3, g_bl3);

    static cudaStream_t s1 = nullptr, s2 = nullptr;
    static cudaEvent_t evRoot = nullptr, evVC = nullptr, evQO = nullptr;
    if (!s1) {
        cudaStreamCreateWithFlags(&s1, cudaStreamNonBlocking);
        cudaStreamCreateWithFlags(&s2, cudaStreamNonBlocking);
        cudaEventCreateWithFlags(&evRoot, cudaEventDisableTiming);
        cudaEventCreateWithFlags(&evVC, cudaEventDisableTiming);
        cudaEventCreateWithFlags(&evQO, cudaEventDisableTiming);
        cudaFuncSetAttribute(mma_gemm_kernel,
                             cudaFuncAttributeMaxDynamicSharedMemorySize, SMEM_MMA);
    }

    const int MBIG = B_ * N_;   // 32768
    const int MSM = B_ * A_;    // 64
    dim3 gsm(8, 1);
    dim3 gbig(8, MBIG / 128);
    dim3 gmma(1024 / BN, MBIG / BM);       // (8, 256)
    dim3 gsw(32, 32);
    dim3 bsw(32, 8);
    const int SA_BLK = (MBIG * D_ / 8) / 256;   // 16384

    // ---- fork side streams ----
    cudaEventRecord(evRoot, 0);
    cudaStreamWaitEvent(s1, evRoot, 0);
    cudaStreamWaitEvent(s2, evRoot, 0);

    // s1: v_c pipeline
    split_w_bf16<<<gsw, bsw, 0, s1>>>(W_vc, p_bh1, p_bl1);
    split_a_bf16<<<SA_BLK, 256, 0, s1>>>(value, p_ah, p_al);
    mma_gemm_kernel<<<gmma, 256, SMEM_MMA, s1>>>(p_ah, p_al, p_bh1, p_bl1, b_vc, p_vc);
    cudaEventRecord(evVC, s1);

    // s2: q_o pipeline + proj weight split
    split_w_bf16<<<gsw, bsw, 0, s2>>>(W_qo, p_bh2, p_bl2);
    split_a_bf16<<<SA_BLK, 256, 0, s2>>>(query, p_ah2, p_al2);
    mma_gemm_kernel<<<gmma, 256, SMEM_MMA, s2>>>(p_ah2, p_al2, p_bh2, p_bl2, b_qo, p_qo);
    split_w_bf16<<<gsw, bsw, 0, s2>>>(W_proj, p_bh3, p_bl3);
    cudaEventRecord(evQO, s2);

    // s0: flip-determining path (bit-identical numerics)
    mean_kernel<<<(B_ * A_ * D_) / 256, 256>>>(query);
    sgemm_bias<<<gsm, 256>>>(p_raw, W_agent, b_agent, p_tok, MSM);
    sgemm_bias<<<gsm, 256>>>(p_tok, W_qa, b_qa, p_qa, MSM);
    sgemm_bias<<<gbig, 256>>>(key, W_kc, b_kc, p_kc, MBIG);
    agent_scores_kernel<<<dim3(B_ * H_, S_ / 256), 256>>>();
    topk_softmax_kernel<<<B_ * H_ * A_, 512>>>(out_attn_agent_w);

    cudaStreamWaitEvent(0, evVC, 0);
    agent_out_kernel<<<B_ * H_, 512>>>(out_attn_agent_w);
    sgemm_bias<<<gsm, 256>>>(p_aout, W_ka, b_ka, p_ka, MSM);
    sgemm_bias<<<gsm, 256>>>(p_aout, W_va, b_va, p_va, MSM);

    cudaStreamWaitEvent(0, evQO, 0);
    final_attn_kernel<<<dim3(B_ * H_, N_ / 256), 256>>>(out_attn_final);
    mma_gemm_kernel<<<gmma, 256, SMEM_MMA>>>(p_ah, p_al, p_bh3, p_bl3, b_proj, out0);
}

// round 16
// speedup vs baseline: 1.4715x; 1.0221x over previous
#include <cuda_runtime.h>
#include <cuda_bf16.h>
#include <cstddef>
#include <cstdint>

#define B_ 8
#define N_ 4096
#define S_ 4096
#define D_ 1024
#define H_ 16
#define A_ 8
#define DH 64
#define NA 512
#define KKEEP 2048
#define SCALE_ 0.125f

// bf16 mma tiling: BM=128, BN=128, BK=32 (2 x k16 steps), pitch 80B rows
#define BM 128
#define BN 128
#define ARRB 10240              // bytes per array: 128 rows * 80
#define STAGE_B 40960           // Ah+Al+Bh+Bl
#define SMEM_MMA 81920          // 2 stages

__device__ float g_kc[(size_t)B_ * S_ * D_];
__device__ float g_vc[(size_t)B_ * S_ * D_];
__device__ float g_qo[(size_t)B_ * N_ * D_];
__device__ float g_attn_agent[(size_t)B_ * H_ * A_ * S_];
__device__ float g_agent_raw[B_ * A_ * D_];
__device__ float g_agent_tok[B_ * A_ * D_];
__device__ float g_qa[B_ * A_ * D_];
__device__ float g_ka[B_ * A_ * D_];
__device__ float g_va[B_ * A_ * D_];
__device__ float g_agent_out[B_ * A_ * D_];
// bf16 split operands
__device__ __nv_bfloat16 g_ah[(size_t)B_ * N_ * D_];
__device__ __nv_bfloat16 g_al[(size_t)B_ * N_ * D_];
__device__ __nv_bfloat16 g_ah2[(size_t)B_ * N_ * D_];
__device__ __nv_bfloat16 g_al2[(size_t)B_ * N_ * D_];
__device__ __nv_bfloat16 g_bh1[(size_t)D_ * D_], g_bl1[(size_t)D_ * D_];
__device__ __nv_bfloat16 g_bh2[(size_t)D_ * D_], g_bl2[(size_t)D_ * D_];
__device__ __nv_bfloat16 g_bh3[(size_t)D_ * D_], g_bl3[(size_t)D_ * D_];

__device__ __forceinline__ uint32_t smem_u32(const void* p) {
    uint32_t a;
    asm("{ .reg .u64 t; cvta.to.shared.u64 t, %1; cvt.u32.u64 %0, t; }" : "=r"(a) : "l"(p));
    return a;
}
#define CP_ASYNC16(dst, src) \
    asm volatile("cp.async.cg.shared.global [%0], [%1], 16;" :: "r"(dst), "l"(src) : "memory")
#define CP_COMMIT() asm volatile("cp.async.commit_group;" ::: "memory")
#define CP_WAITN(n) asm volatile("cp.async.wait_group %0;" :: "n"(n) : "memory")

#define LDSM_X4(r0, r1, r2, r3, addr) \
    asm volatile("ldmatrix.sync.aligned.m8n8.x4.shared.b16 {%0,%1,%2,%3}, [%4];" \
                 : "=r"(r0), "=r"(r1), "=r"(r2), "=r"(r3) : "r"(addr))

__device__ __forceinline__ void mma16(float* d, const uint32_t* a, uint32_t b0, uint32_t b1) {
    asm volatile(
        "mma.sync.aligned.m16n8k16.row.col.f32.bf16.bf16.f32 "
        "{%0,%1,%2,%3}, {%4,%5,%6,%7}, {%8,%9}, {%0,%1,%2,%3};"
        : "+f"(d[0]), "+f"(d[1]), "+f"(d[2]), "+f"(d[3])
        : "r"(a[0]), "r"(a[1]), "r"(a[2]), "r"(a[3]), "r"(b0), "r"(b1));
}

__device__ __forceinline__ void bf16_split(float v, __nv_bfloat16& h, __nv_bfloat16& l) {
    h = __float2bfloat16_rn(v);
    l = __float2bfloat16_rn(v - __bfloat162float(h));
}
__device__ __forceinline__ uint32_t pk2(__nv_bfloat16 a, __nv_bfloat16 b) {
    return (uint32_t)__bfloat16_as_ushort(a) | ((uint32_t)__bfloat16_as_ushort(b) << 16);
}

// A[M,1024] fp32 -> bf16 hi/lo (row-major). 8 floats/thread.
__global__ __launch_bounds__(256) void split_a_bf16(const float* __restrict__ a,
                                                    __nv_bfloat16* __restrict__ hi,
                                                    __nv_bfloat16* __restrict__ lo) {
    size_t i = (size_t)blockIdx.x * 256 + threadIdx.x;
    const float4* s4 = (const float4*)a + i * 2;
    float4 x = s4[0], y = s4[1];
    float v[8] = {x.x, x.y, x.z, x.w, y.x, y.y, y.z, y.w};
    uint32_t hp[4], lp[4];
#pragma unroll
    for (int j = 0; j < 4; j++) {
        __nv_bfloat16 h0, l0, h1, l1;
        bf16_split(v[2 * j], h0, l0);
        bf16_split(v[2 * j + 1], h1, l1);
        hp[j] = pk2(h0, h1);
        lp[j] = pk2(l0, l1);
    }
    *(uint4*)(hi + i * 8) = make_uint4(hp[0], hp[1], hp[2], hp[3]);
    *(uint4*)(lo + i * 8) = make_uint4(lp[0], lp[1], lp[2], lp[3]);
}

// W[k][n] fp32 -> bf16 hi/lo transposed [n][k]
__global__ __launch_bounds__(256) void split_w_bf16(const float* __restrict__ w,
                                                    __nv_bfloat16* __restrict__ hi,
                                                    __nv_bfloat16* __restrict__ lo) {
    __shared__ float t[32][33];
    int k0 = blockIdx.y * 32, n0 = blockIdx.x * 32;
    int tx = threadIdx.x, ty = threadIdx.y;
    for (int i = ty; i < 32; i += 8)
        t[i][tx] = w[(size_t)(k0 + i) * 1024 + n0 + tx];
    __syncthreads();
    for (int i = ty; i < 32; i += 8) {
        __nv_bfloat16 h, l;
        bf16_split(t[tx][i], h, l);
        hi[(size_t)(n0 + i) * 1024 + k0 + tx] = h;
        lo[(size_t)(n0 + i) * 1024 + k0 + tx] = l;
    }
}

// C[M,1024] = (Ah+Al)@(Bh+Bl)^T + bias, 3xBF16 m16n8k16 with ldmatrix frags.
// grid=(8, M/128), 2 CTA/SM
__global__ __launch_bounds__(256, 2) void mma_gemm_kernel(
    const __nv_bfloat16* __restrict__ gAh, const __nv_bfloat16* __restrict__ gAl,
    const __nv_bfloat16* __restrict__ gBh, const __nv_bfloat16* __restrict__ gBl,
    const float* __restrict__ bias, float* __restrict__ C) {
    extern __shared__ __align__(16) char smem[];
    const uint32_t sb = smem_u32(smem);
    const int tid = threadIdx.x;
    const int row0 = blockIdx.y * BM;
    const int col0 = blockIdx.x * BN;
    const int w = tid >> 5;
    const int lane = tid & 31;
    const int wm = w >> 2;
    const int wn = w & 3;
    const int g = lane >> 2;
    const int ctg = lane & 3;
    // ldmatrix lane address components
    const int a_row = ((lane >> 3) & 1) * 8 + (lane & 7);
    const int a_kb = ((lane >> 4) & 1) * 16;
    const int b_nrow = ((lane >> 4) & 1) * 8 + (lane & 7);
    const int b_kb = ((lane >> 3) & 1) * 16;

    float acc[4][4][4];
#pragma unroll
    for (int mt = 0; mt < 4; mt++)
#pragma unroll
        for (int nt = 0; nt < 4; nt++)
#pragma unroll
            for (int r = 0; r < 4; r++) acc[mt][nt][r] = 0.f;

    auto load_stage = [&](int s, int kt) {
        uint32_t st = sb + s * STAGE_B;
        const int k0 = kt * 32;
#pragma unroll
        for (int j = 0; j < 2; j++) {
            int cid = j * 256 + tid;
            int r = cid >> 2, c = cid & 3;
            uint32_t da = st + r * 80 + c * 16;
            size_t ga = (size_t)(row0 + r) * 1024 + k0 + c * 8;
            CP_ASYNC16(da, gAh + ga);
            CP_ASYNC16(da + ARRB, gAl + ga);
            uint32_t db = st + 2 * ARRB + r * 80 + c * 16;
            size_t gb = (size_t)(col0 + r) * 1024 + k0 + c * 8;
            CP_ASYNC16(db, gBh + gb);
            CP_ASYNC16(db + ARRB, gBl + gb);
        }
        CP_COMMIT();
    };

    load_stage(0, 0);

    for (int kt = 0; kt < 32; kt++) {
        if (kt + 1 < 32) {
            load_stage((kt + 1) & 1, kt + 1);
            CP_WAITN(1);
        } else {
            CP_WAITN(0);
        }
        __syncthreads();
        const uint32_t st = sb + (kt & 1) * STAGE_B;
#pragma unroll
        for (int ks = 0; ks < 2; ks++) {
            const int ko = ks * 32;
            uint32_t ah[4][4], al[4][4];
#pragma unroll
            for (int mt = 0; mt < 4; mt++) {
                uint32_t pa = st + (wm * 64 + mt * 16 + a_row) * 80 + ko + a_kb;
                LDSM_X4(ah[mt][0], ah[mt][1], ah[mt][2], ah[mt][3], pa);
                LDSM_X4(al[mt][0], al[mt][1], al[mt][2], al[mt][3], pa + ARRB);
            }
#pragma unroll
            for (int ntp = 0; ntp < 2; ntp++) {
                uint32_t pb = st + 2 * ARRB + (wn * 32 + ntp * 16 + b_nrow) * 80 + ko + b_kb;
                uint32_t bh0a, bh1a, bh0b, bh1b, bl0a, bl1a, bl0b, bl1b;
                LDSM_X4(bh0a, bh1a, bh0b, bh1b, pb);
                LDSM_X4(bl0a, bl1a, bl0b, bl1b, pb + ARRB);
#pragma unroll
                for (int mt = 0; mt < 4; mt++) {
                    mma16(acc[mt][2 * ntp], ah[mt], bh0a, bh1a);
                    mma16(acc[mt][2 * ntp], ah[mt], bl0a, bl1a);
                    mma16(acc[mt][2 * ntp], al[mt], bh0a, bh1a);
                }
#pragma unroll
                for (int mt = 0; mt < 4; mt++) {
                    mma16(acc[mt][2 * ntp + 1], ah[mt], bh0b, bh1b);
                    mma16(acc[mt][2 * ntp + 1], ah[mt], bl0b, bl1b);
                    mma16(acc[mt][2 * ntp + 1], al[mt], bh0b, bh1b);
                }
            }
        }
        __syncthreads();
    }

#pragma unroll
    for (int mt = 0; mt < 4; mt++) {
        int r = row0 + wm * 64 + mt * 16 + g;
#pragma unroll
        for (int nt = 0; nt < 4; nt++) {
            int c = col0 + wn * 32 + nt * 8 + ctg * 2;
            float b0 = bias[c], b1 = bias[c + 1];
            *(float2*)&C[(size_t)r * 1024 + c] =
                make_float2(acc[mt][nt][0] + b0, acc[mt][nt][1] + b1);
            *(float2*)&C[(size_t)(r + 8) * 1024 + c] =
                make_float2(acc[mt][nt][2] + b0, acc[mt][nt][3] + b1);
        }
    }
}

__global__ void mean_kernel(const float* __restrict__ q) {
    int idx = blockIdx.x * blockDim.x + threadIdx.x;
    int d = idx & (D_ - 1);
    int ba = idx / D_;
    int a = ba & (A_ - 1);
    int b = ba / A_;
    const float* base = q + ((size_t)(b * N_ + a * NA)) * D_ + d;
    float s = 0.f;
#pragma unroll 8
    for (int n = 0; n < NA; n++) s += base[(size_t)n * D_];
    g_agent_raw[idx] = s * (1.0f / NA);
}

// fp32 SGEMM: single smem buffer, register-prefetch of the next K-tile.
// Inner compute loop identical to R1 baseline -> bit-identical results.
__global__ __launch_bounds__(256, 2) void sgemm_bias(
    const float* __restrict__ A, const float* __restrict__ W,
    const float* __restrict__ bias, float* __restrict__ C, int M) {
    __shared__ float As[16][128];
    __shared__ float Bs[16][128];
    const int t = threadIdx.x;
    const int row0 = blockIdx.y * 128;
    const int col0 = blockIdx.x * 128;
    const int tr = t >> 4;
    const int tc = t & 15;
    const int ar0 = (t * 2) >> 2, ac0 = (t * 2) & 3;
    const int ar1 = (t * 2 + 1) >> 2, ac1 = (t * 2 + 1) & 3;
    const int br0 = (t * 2) >> 5, bc0 = (t * 2) & 31;
    const int br1 = (t * 2 + 1) >> 5, bc1 = (t * 2 + 1) & 31;
    const float4 z4 = make_float4(0.f, 0.f, 0.f, 0.f);

    float acc[8][8];
#pragma unroll
    for (int i = 0; i < 8; i++)
#pragma unroll
        for (int j = 0; j < 8; j++) acc[i][j] = 0.f;

    float4 av0 = (row0 + ar0 < M) ? *(const float4*)&A[(size_t)(row0 + ar0) * 1024 + ac0 * 4] : z4;
    float4 av1 = (row0 + ar1 < M) ? *(const float4*)&A[(size_t)(row0 + ar1) * 1024 + ac1 * 4] : z4;
    float4 bv0 = *(const float4*)&W[(size_t)br0 * 1024 + col0 + bc0 * 4];
    float4 bv1 = *(const float4*)&W[(size_t)br1 * 1024 + col0 + bc1 * 4];
    As[ac0 * 4 + 0][ar0] = av0.x;
    As[ac0 * 4 + 1][ar0] = av0.y;
    As[ac0 * 4 + 2][ar0] = av0.z;
    As[ac0 * 4 + 3][ar0] = av0.w;
    As[ac1 * 4 + 0][ar1] = av1.x;
    As[ac1 * 4 + 1][ar1] = av1.y;
    As[ac1 * 4 + 2][ar1] = av1.z;
    As[ac1 * 4 + 3][ar1] = av1.w;
    *(float4*)&Bs[br0][bc0 * 4] = bv0;
    *(float4*)&Bs[br1][bc1 * 4] = bv1;
    __syncthreads();

    for (int k0 = 0; k0 < 1024; k0 += 16) {
        const bool more = (k0 + 16 < 1024);
        if (more) {
            av0 = (row0 + ar0 < M)
                      ? *(const float4*)&A[(size_t)(row0 + ar0) * 1024 + k0 + 16 + ac0 * 4] : z4;
            av1 = (row0 + ar1 < M)
                      ? *(const float4*)&A[(size_t)(row0 + ar1) * 1024 + k0 + 16 + ac1 * 4] : z4;
            bv0 = *(const float4*)&W[(size_t)(k0 + 16 + br0) * 1024 + col0 + bc0 * 4];
            bv1 = *(const float4*)&W[(size_t)(k0 + 16 + br1) * 1024 + col0 + bc1 * 4];
        }
#pragma unroll
        for (int k = 0; k < 16; k++) {
            float ra[8], rb[8];
#pragma unroll
            for (int i = 0; i < 8; i++) ra[i] = As[k][tr * 8 + i];
#pragma unroll
            for (int j = 0; j < 8; j++) rb[j] = Bs[k][tc * 8 + j];
#pragma unroll
            for (int i = 0; i < 8; i++)
#pragma unroll
                for (int j = 0; j < 8; j++) acc[i][j] += ra[i] * rb[j];
        }
        if (more) {
            __syncthreads();
            As[ac0 * 4 + 0][ar0] = av0.x;
            As[ac0 * 4 + 1][ar0] = av0.y;
            As[ac0 * 4 + 2][ar0] = av0.z;
            As[ac0 * 4 + 3][ar0] = av0.w;
            As[ac1 * 4 + 0][ar1] = av1.x;
            As[ac1 * 4 + 1][ar1] = av1.y;
            As[ac1 * 4 + 2][ar1] = av1.z;
            As[ac1 * 4 + 3][ar1] = av1.w;
            *(float4*)&Bs[br0][bc0 * 4] = bv0;
            *(float4*)&Bs[br1][bc1 * 4] = bv1;
            __syncthreads();
        }
    }

    float bv[8];
#pragma unroll
    for (int j = 0; j < 8; j++) bv[j] = bias[col0 + tc * 8 + j];
#pragma unroll
    for (int i = 0; i < 8; i++) {
        int r = row0 + tr * 8 + i;
        if (r < M) {
            float4 o0 = make_float4(acc[i][0] + bv[0], acc[i][1] + bv[1],
                                    acc[i][2] + bv[2], acc[i][3] + bv[3]);
            float4 o1 = make_float4(acc[i][4] + bv[4], acc[i][5] + bv[5],
                                    acc[i][6] + bv[6], acc[i][7] + bv[7]);
            *(float4*)&C[(size_t)r * 1024 + col0 + tc * 8 + 0] = o0;
            *(float4*)&C[(size_t)r * 1024 + col0 + tc * 8 + 4] = o1;
        }
    }
}

__global__ __launch_bounds__(256) void agent_scores_kernel() {
    int bh = blockIdx.x;
    int b = bh / H_, h = bh % H_;
    int t = threadIdx.x;
    int s = blockIdx.y * 256 + t;
    __shared__ float qs[A_][DH];
    for (int i = t; i < A_ * DH; i += 256) {
        int a = i / DH, d = i % DH;
        qs[a][d] = g_qa[(b * A_ + a) * D_ + h * DH + d];
    }
    __syncthreads();
    const float4* krow = (const float4*)&g_kc[((size_t)b * S_ + s) * D_ + h * DH];
    float acc[A_];
#pragma unroll
    for (int a = 0; a < A_; a++) acc[a] = 0.f;
#pragma unroll
    for (int d4 = 0; d4 < DH / 4; d4++) {
        float4 kv = krow[d4];
#pragma unroll
        for (int a = 0; a < A_; a++) {
            acc[a] += kv.x * qs[a][d4 * 4 + 0] + kv.y * qs[a][d4 * 4 + 1] +
                      kv.z * qs[a][d4 * 4 + 2] + kv.w * qs[a][d4 * 4 + 3];
        }
    }
#pragma unroll
    for (int a = 0; a < A_; a++)
        g_attn_agent[(((size_t)bh) * A_ + a) * S_ + s] = acc[a] * SCALE_;
}

__global__ __launch_bounds__(512) void topk_softmax_kernel(float* __restrict__ w_out) {
    __shared__ float v[S_];
    __shared__ float srt[S_];
    __shared__ float red[512];
    int row = blockIdx.x;
    int t = threadIdx.x;
    const float* src = g_attn_agent + (size_t)row * S_;
    for (int i = t; i < S_; i += 512) {
        float x = src[i];
        v[i] = x;
        srt[i] = x;
    }
    __syncthreads();
    for (int k = 2; k <= S_; k <<= 1) {
        for (int j = k >> 1; j > 0; j >>= 1) {
            for (int i = t; i < S_; i += 512) {
                int ixj = i ^ j;
                if (ixj > i) {
                    bool up = ((i & k) == 0);
                    float a = srt[i], b = srt[ixj];
                    if ((a > b) == up) { srt[i] = b; srt[ixj] = a; }
                }
            }
            __syncthreads();
        }
    }
    float thresh = srt[S_ - KKEEP];
    float mx = srt[S_ - 1];
    float lsum = 0.f;
    for (int i = t; i < S_; i += 512) {
        float x = v[i];
        float e = (x >= thresh) ? expf(x - mx) : 0.f;
        v[i] = e;
        lsum += e;
    }
    red[t] = lsum;
    __syncthreads();
    for (int o = 256; o > 0; o >>= 1) {
        if (t < o) red[t] += red[t + o];
        __syncthreads();
    }
    float inv = 1.f / red[0];
    float* dst = w_out + (size_t)row * S_;
    for (int i = t; i < S_; i += 512) dst[i] = v[i] * inv;
}

__global__ __launch_bounds__(512) void agent_out_kernel(const float* __restrict__ w) {
    int bh = blockIdx.x;
    int b = bh / H_, h = bh % H_;
    int t = threadIdx.x;
    int a = t / DH, d = t % DH;
    __shared__ float ws[A_][256];
    const float* wbase = w + ((size_t)bh * A_) * S_;
    const float* vbase = g_vc + ((size_t)b * S_) * D_ + h * DH;
    float acc = 0.f;
    for (int s0 = 0; s0 < S_; s0 += 256) {
        for (int i = t; i < A_ * 256; i += 512) {
            int aa = i >> 8, ss = i & 255;
            ws[aa][ss] = wbase[(size_t)aa * S_ + s0 + ss];
        }
        __syncthreads();
#pragma unroll 8
        for (int ss = 0; ss < 256; ss++)
            acc += ws[a][ss] * vbase[(size_t)(s0 + ss) * D_ + d];
        __syncthreads();
    }
    g_agent_out[(b * A_ + a) * D_ + h * DH + d] = acc;
}

// writes attn_final + bf16 hi/lo split of outpre into g_ah/g_al
__global__ __launch_bounds__(256) void final_attn_kernel(float* __restrict__ attn_out) {
    int bh = blockIdx.x;
    int b = bh / H_, h = bh % H_;
    int t = threadIdx.x;
    int n = blockIdx.y * 256 + t;
    __shared__ float ks[A_][DH], vs[A_][DH];
    for (int i = t; i < A_ * DH; i += 256) {
        int a = i / DH, d = i % DH;
        ks[a][d] = g_ka[(b * A_ + a) * D_ + h * DH + d];
        vs[a][d] = g_va[(b * A_ + a) * D_ + h * DH + d];
    }
    __syncthreads();
    const float4* qrow = (const float4*)&g_qo[((size_t)b * N_ + n) * D_ + h * DH];
    float sc[A_];
#pragma unroll
    for (int a = 0; a < A_; a++) sc[a] = 0.f;
#pragma unroll
    for (int d4 = 0; d4 < DH / 4; d4++) {
        float4 q = qrow[d4];
#pragma unroll
        for (int a = 0; a < A_; a++) {
            sc[a] += q.x * ks[a][d4 * 4 + 0] + q.y * ks[a][d4 * 4 + 1] +
                     q.z * ks[a][d4 * 4 + 2] + q.w * ks[a][d4 * 4 + 3];
        }
    }
    float mx = -1e30f;
#pragma unroll
    for (int a = 0; a < A_; a++) {
        sc[a] *= SCALE_;
        mx = fmaxf(mx, sc[a]);
    }
    float sum = 0.f;
#pragma unroll
    for (int a = 0; a < A_; a++) {
        sc[a] = expf(sc[a] - mx);
        sum += sc[a];
    }
    float inv = 1.f / sum;
#pragma unroll
    for (int a = 0; a < A_; a++) sc[a] *= inv;
    float* ao = attn_out + (((size_t)bh) * N_ + n) * A_;
#pragma unroll
    for (int a = 0; a < A_; a++) ao[a] = sc[a];
    const size_t obase = ((size_t)b * N_ + n) * D_ + h * DH;
#pragma unroll
    for (int d4 = 0; d4 < DH / 4; d4++) {
        float4 o = make_float4(0.f, 0.f, 0.f, 0.f);
#pragma unroll
        for (int a = 0; a < A_; a++) {
            float w = sc[a];
            o.x += w * vs[a][d4 * 4 + 0];
            o.y += w * vs[a][d4 * 4 + 1];
            o.z += w * vs[a][d4 * 4 + 2];
            o.w += w * vs[a][d4 * 4 + 3];
        }
        __nv_bfloat16 h0, l0, h1, l1, h2, l2, h3, l3;
        bf16_split(o.x, h0, l0);
        bf16_split(o.y, h1, l1);
        bf16_split(o.z, h2, l2);
        bf16_split(o.w, h3, l3);
        *(uint2*)(g_ah + obase + d4 * 4) = make_uint2(pk2(h0, h1), pk2(h2, h3));
        *(uint2*)(g_al + obase + d4 * 4) = make_uint2(pk2(l0, l1), pk2(l2, l3));
    }
}

extern "C" void kernel_launch(void* const* d_in, const int* in_sizes, int n_in,
                              void* d_out, int out_size) {
    const float* query = (const float*)d_in[0];
    const float* key = (const float*)d_in[1];
    const float* value = (const float*)d_in[2];
    const float* W_agent = (const float*)d_in[3];
    const float* b_agent = (const float*)d_in[4];
    const float* W_qa = (const float*)d_in[5];
    const float* b_qa = (const float*)d_in[6];
    const float* W_kc = (const float*)d_in[7];
    const float* b_kc = (const float*)d_in[8];
    const float* W_vc = (const float*)d_in[9];
    const float* b_vc = (const float*)d_in[10];
    const float* W_qo = (const float*)d_in[11];
    const float* b_qo = (const float*)d_in[12];
    const float* W_ka = (const float*)d_in[13];
    const float* b_ka = (const float*)d_in[14];
    const float* W_va = (const float*)d_in[15];
    const float* b_va = (const float*)d_in[16];
    const float* W_proj = (const float*)d_in[17];
    const float* b_proj = (const float*)d_in[18];

    float* out0 = (float*)d_out;
    float* out_attn_final = out0 + (size_t)B_ * N_ * D_;
    float* out_attn_agent_w = out_attn_final + (size_t)B_ * H_ * N_ * A_;

    float *p_raw, *p_tok, *p_qa, *p_kc, *p_vc, *p_qo, *p_ka, *p_va, *p_aout;
    __nv_bfloat16 *p_ah, *p_al, *p_ah2, *p_al2, *p_bh1, *p_bl1, *p_bh2, *p_bl2, *p_bh3, *p_bl3;
    cudaGetSymbolAddress((void**)&p_raw, g_agent_raw);
    cudaGetSymbolAddress((void**)&p_tok, g_agent_tok);
    cudaGetSymbolAddress((void**)&p_qa, g_qa);
    cudaGetSymbolAddress((void**)&p_kc, g_kc);
    cudaGetSymbolAddress((void**)&p_vc, g_vc);
    cudaGetSymbolAddress((void**)&p_qo, g_qo);
    cudaGetSymbolAddress((void**)&p_ka, g_ka);
    cudaGetSymbolAddress((void**)&p_va, g_va);
    cudaGetSymbolAddress((void**)&p_aout, g_agent_out);
    cudaGetSymbolAddress((void**)&p_ah, g_ah);
    cudaGetSymbolAddress((void**)&p_al, g_al);
    cudaGetSymbolAddress((void**)&p_ah2, g_ah2);
    cudaGetSymbolAddress((void**)&p_al2, g_al2);
    cudaGetSymbolAddress((void**)&p_bh1, g_bh1);
    cudaGetSymbolAddress((void**)&p_bl1, g_bl1);
    cudaGetSymbolAddress((void**)&p_bh2, g_bh2);
    cudaGetSymbolAddress((void**)&p_bl2, g_bl2);
    cudaGetSymbolAddress((void**)&p_bh3, g_bh3);
    cudaGetSymbolAddress((void**)&p_bl3, g_bl3);

    static cudaStream_t s1 = nullptr, s2 = nullptr;
    static cudaEvent_t evRoot = nullptr, evVC = nullptr, evQO = nullptr;
    if (!s1) {
        cudaStreamCreateWithFlags(&s1, cudaStreamNonBlocking);
        cudaStreamCreateWithFlags(&s2, cudaStreamNonBlocking);
        cudaEventCreateWithFlags(&evRoot, cudaEventDisableTiming);
        cudaEventCreateWithFlags(&evVC, cudaEventDisableTiming);
        cudaEventCreateWithFlags(&evQO, cudaEventDisableTiming);
        cudaFuncSetAttribute(mma_gemm_kernel,
                             cudaFuncAttributeMaxDynamicSharedMemorySize, SMEM_MMA);
    }

    const int MBIG = B_ * N_;   // 32768
    const int MSM = B_ * A_;    // 64
    dim3 gsm(8, 1);
    dim3 gbig(8, MBIG / 128);
    dim3 gmma(1024 / BN, MBIG / BM);       // (8, 256)
    dim3 gsw(32, 32);
    dim3 bsw(32, 8);
    const int SA_BLK = (MBIG * D_ / 8) / 256;   // 16384

    // ---- fork side streams ----
    cudaEventRecord(evRoot, 0);
    cudaStreamWaitEvent(s1, evRoot, 0);
    cudaStreamWaitEvent(s2, evRoot, 0);

    // s1: v_c pipeline
    split_w_bf16<<<gsw, bsw, 0, s1>>>(W_vc, p_bh1, p_bl1);
    split_a_bf16<<<SA_BLK, 256, 0, s1>>>(value, p_ah, p_al);
    mma_gemm_kernel<<<gmma, 256, SMEM_MMA, s1>>>(p_ah, p_al, p_bh1, p_bl1, b_vc, p_vc);
    cudaEventRecord(evVC, s1);

    // s2: q_o pipeline + proj weight split
    split_w_bf16<<<gsw, bsw, 0, s2>>>(W_qo, p_bh2, p_bl2);
    split_a_bf16<<<SA_BLK, 256, 0, s2>>>(query, p_ah2, p_al2);
    mma_gemm_kernel<<<gmma, 256, SMEM_MMA, s2>>>(p_ah2, p_al2, p_bh2, p_bl2, b_qo, p_qo);
    split_w_bf16<<<gsw, bsw, 0, s2>>>(W_proj, p_bh3, p_bl3);
    cudaEventRecord(evQO, s2);

    // s0: flip-determining path (bit-identical numerics)
    mean_kernel<<<(B_ * A_ * D_) / 256, 256>>>(query);
    sgemm_bias<<<gsm, 256>>>(p_raw, W_agent, b_agent, p_tok, MSM);
    sgemm_bias<<<gsm, 256>>>(p_tok, W_qa, b_qa, p_qa, MSM);
    sgemm_bias<<<gbig, 256>>>(key, W_kc, b_kc, p_kc, MBIG);
    agent_scores_kernel<<<dim3(B_ * H_, S_ / 256), 256>>>();
    topk_softmax_kernel<<<B_ * H_ * A_, 512>>>(out_attn_agent_w);

    cudaStreamWaitEvent(0, evVC, 0);
    agent_out_kernel<<<B_ * H_, 512>>>(out_attn_agent_w);
    sgemm_bias<<<gsm, 256>>>(p_aout, W_ka, b_ka, p_ka, MSM);
    sgemm_bias<<<gsm, 256>>>(p_aout, W_va, b_va, p_va, MSM);

    cudaStreamWaitEvent(0, evQO, 0);
    final_attn_kernel<<<dim3(B_ * H_, N_ / 256), 256>>>(out_attn_final);
    mma_gemm_kernel<<<gmma, 256, SMEM_MMA>>>(p_ah, p_al, p_bh3, p_bl3, b_proj, out0);
}